// round 13
// baseline (speedup 1.0000x reference)
#include <cuda_runtime.h>
#include <cuda_bf16.h>
#include <cstdint>

// ---------------------------------------------------------------------------
// Problem constants
// ---------------------------------------------------------------------------
#define DIMM 4096        // model dim (= N_HEAD * HEAD_DIM)
#define KVD  1024        // kv proj dim (= N_KV_HEAD * HEAD_DIM)
#define SEQ  2048
#define TOKS 4096        // B * SEQ
#define NQKV 6144        // fused projection width: 4096 Q + 1024 K + 1024 V
#define KP   2048        // K in bf16 pairs (K = 4096 for both GEMMs)

// ---------------------------------------------------------------------------
// Scratch (no cudaMalloc allowed).
// hi/lo buffers hold bf16 split-precision operands packed as (k_odd<<16)|k_even.
// ---------------------------------------------------------------------------
__device__ uint32_t g_Xhi[TOKS * KP];    // 32 MB
__device__ uint32_t g_Xlo[TOKS * KP];    // 32 MB
__device__ uint32_t g_Whi[NQKV * KP];    // 48 MB  wq|wk|wv
__device__ uint32_t g_Wlo[NQKV * KP];    // 48 MB
__device__ uint32_t g_WOhi[DIMM * KP];   // 32 MB
__device__ uint32_t g_WOlo[DIMM * KP];   // 32 MB
__device__ float    g_Q[TOKS * DIMM];    // 64 MB (tf32-exact, rope fused)
__device__ float    g_K[TOKS * KVD];     // 16 MB (tf32-exact, rope fused)
__device__ float    g_V[TOKS * KVD];     // 16 MB (tf32-exact)
__device__ uint32_t g_Ohi[TOKS * KP];    // 32 MB (flash output, split-packed)
__device__ uint32_t g_Olo[TOKS * KP];    // 32 MB

// ---------------------------------------------------------------------------
// Helpers
// ---------------------------------------------------------------------------
__device__ __forceinline__ uint32_t f2tf(float f) {
    uint32_t r;
    asm volatile("cvt.rna.tf32.f32 %0, %1;" : "=r"(r) : "f"(f));
    return r;
}
__device__ __forceinline__ float rtf(float f) { return __uint_as_float(f2tf(f)); }

__device__ __forceinline__ void cp_async16(void* smem, const void* gmem) {
    uint32_t s = (uint32_t)__cvta_generic_to_shared(smem);
    asm volatile("cp.async.cg.shared.global [%0], [%1], 16;\n" :: "r"(s), "l"(gmem) : "memory");
}
__device__ __forceinline__ void cp_async_commit() {
    asm volatile("cp.async.commit_group;\n" ::: "memory");
}
template<int N>
__device__ __forceinline__ void cp_async_wait() {
    asm volatile("cp.async.wait_group %0;\n" :: "n"(N) : "memory");
}

// bf16 m16n8k16: D += A(16x16,row) * B(16x8,col), f32 accum
__device__ __forceinline__ void mma_bf16(float& c0, float& c1, float& c2, float& c3,
                                         uint32_t a0, uint32_t a1, uint32_t a2, uint32_t a3,
                                         uint32_t b0, uint32_t b1) {
    asm volatile(
        "mma.sync.aligned.m16n8k16.row.col.f32.bf16.bf16.f32 "
        "{%0,%1,%2,%3}, {%4,%5,%6,%7}, {%8,%9}, {%0,%1,%2,%3};\n"
        : "+f"(c0), "+f"(c1), "+f"(c2), "+f"(c3)
        : "r"(a0), "r"(a1), "r"(a2), "r"(a3), "r"(b0), "r"(b1));
}

// tf32 m16n8k8 (flash kernel)
__device__ __forceinline__ void mma_tf32(float& c0, float& c1, float& c2, float& c3,
                                         uint32_t a0, uint32_t a1, uint32_t a2, uint32_t a3,
                                         uint32_t b0, uint32_t b1) {
    asm volatile(
        "mma.sync.aligned.m16n8k8.row.col.f32.tf32.tf32.f32 "
        "{%0,%1,%2,%3}, {%4,%5,%6,%7}, {%8,%9}, {%0,%1,%2,%3};\n"
        : "+f"(c0), "+f"(c1), "+f"(c2), "+f"(c3)
        : "r"(a0), "r"(a1), "r"(a2), "r"(a3), "r"(b0), "r"(b1));
}

__device__ __forceinline__ void split_pack(float a, float b, uint32_t& hi, uint32_t& lo) {
    __nv_bfloat16 h0 = __float2bfloat16_rn(a);
    __nv_bfloat16 h1 = __float2bfloat16_rn(b);
    __nv_bfloat16 l0 = __float2bfloat16_rn(a - __bfloat162float(h0));
    __nv_bfloat16 l1 = __float2bfloat16_rn(b - __bfloat162float(h1));
    hi = ((uint32_t)__bfloat16_as_ushort(h1) << 16) | __bfloat16_as_ushort(h0);
    lo = ((uint32_t)__bfloat16_as_ushort(l1) << 16) | __bfloat16_as_ushort(l0);
}

// ---------------------------------------------------------------------------
// Split-precision packing prepass: float pairs -> (hi, lo) uint32 pair buffers.
// 4 pairs per thread; all sizes divisible by 1024 pairs.
// ---------------------------------------------------------------------------
__global__ void pack_bf16_kernel(const float2* __restrict__ src,
                                 uint32_t* __restrict__ hi, uint32_t* __restrict__ lo) {
    int base = blockIdx.x * 1024 + threadIdx.x;
    #pragma unroll
    for (int j = 0; j < 4; ++j) {
        int p = base + j * 256;
        float2 v = src[p];
        uint32_t h, l;
        split_pack(v.x, v.y, h, l);
        hi[p] = h; lo[p] = l;
    }
}

// ---------------------------------------------------------------------------
// Split-precision bf16 GEMM core. Block 128x128, BK = 16 pairs (k32),
// 128 threads = 4 warps of 64x64 tiles, 2 CTAs/SM, double-buffered smem.
// Stage: Ahi|Alo|Bhi|Blo, each [128][20] uint32 (pair-stride 20 = 4 mod 32
// -> conflict-free fragment LDS; 80B rows, 16B-aligned segments).
// Per k16 chunk: acc += Ah*Bh + Ah*Bl + Al*Bh   (ll term ~2^-18, dropped).
// ---------------------------------------------------------------------------
#define GBM 128
#define GBN 128
#define PBK 16
#define PST 20
#define ABUF (128 * PST)
#define STG  (4 * ABUF)
#define GEMM_SMEM (2 * STG * 4)   // 81920 bytes

#define BF16_GEMM_MAINLOOP(AHI_, ALO_, WHI_, WLO_)                                     \
    float acc[4][8][4];                                                                \
    _Pragma("unroll")                                                                  \
    for (int i = 0; i < 4; ++i)                                                        \
        _Pragma("unroll")                                                              \
        for (int j = 0; j < 8; ++j) {                                                  \
            acc[i][j][0] = 0.f; acc[i][j][1] = 0.f;                                    \
            acc[i][j][2] = 0.f; acc[i][j][3] = 0.f;                                    \
        }                                                                              \
    const int T = KP / PBK;                                                            \
    auto load_stage = [&](int slot, int tt) {                                          \
        uint32_t* stg = smw + slot * STG;                                              \
        _Pragma("unroll")                                                              \
        for (int e = tid; e < 2048; e += 128) {                                        \
            int r = e >> 4, s = e & 15;          /* s uniform per thread */            \
            uint32_t* dst = stg + (s >> 2) * ABUF + r * PST + (s & 3) * 4;             \
            const uint32_t* src;                                                       \
            if (s < 8)                                                                 \
                src = ((s < 4) ? (AHI_) : (ALO_))                                      \
                      + (size_t)(bm + r) * KP + tt * PBK + (s & 3) * 4;                \
            else                                                                       \
                src = ((s < 12) ? (WHI_) : (WLO_))                                     \
                      + (size_t)(bn + r) * KP + tt * PBK + (s & 3) * 4;                \
            cp_async16(dst, src);                                                      \
        }                                                                              \
        cp_async_commit();                                                             \
    };                                                                                 \
    load_stage(0, 0);                                                                  \
    for (int t = 0; t < T; ++t) {                                                      \
        cp_async_wait<0>();                                                            \
        __syncthreads();                                                               \
        if (t + 1 < T) load_stage((t + 1) & 1, t + 1);                                 \
        const uint32_t* stg = smw + (t & 1) * STG;                                     \
        _Pragma("unroll")                                                              \
        for (int cc = 0; cc < 2; ++cc) {                                               \
            uint32_t ah[4][4], al[4][4];                                               \
            _Pragma("unroll")                                                          \
            for (int mi = 0; mi < 4; ++mi) {                                           \
                int base = (wm * 64 + mi * 16 + (lane >> 2)) * PST                     \
                           + cc * 8 + (lane & 3);                                      \
                ah[mi][0] = stg[base];                                                 \
                ah[mi][1] = stg[base + 8 * PST];                                       \
                ah[mi][2] = stg[base + 4];                                             \
                ah[mi][3] = stg[base + 8 * PST + 4];                                   \
                al[mi][0] = stg[ABUF + base];                                          \
                al[mi][1] = stg[ABUF + base + 8 * PST];                                \
                al[mi][2] = stg[ABUF + base + 4];                                      \
                al[mi][3] = stg[ABUF + base + 8 * PST + 4];                            \
            }                                                                          \
            _Pragma("unroll")                                                          \
            for (int ni = 0; ni < 8; ++ni) {                                           \
                int base = 2 * ABUF + (wn * 64 + ni * 8 + (lane >> 2)) * PST           \
                           + cc * 8 + (lane & 3);                                      \
                uint32_t bh0 = stg[base], bh1 = stg[base + 4];                         \
                uint32_t bl0 = stg[ABUF + base], bl1 = stg[ABUF + base + 4];           \
                _Pragma("unroll")                                                      \
                for (int mi = 0; mi < 4; ++mi) {                                       \
                    mma_bf16(acc[mi][ni][0], acc[mi][ni][1],                           \
                             acc[mi][ni][2], acc[mi][ni][3],                           \
                             ah[mi][0], ah[mi][1], ah[mi][2], ah[mi][3], bh0, bh1);    \
                    mma_bf16(acc[mi][ni][0], acc[mi][ni][1],                           \
                             acc[mi][ni][2], acc[mi][ni][3],                           \
                             ah[mi][0], ah[mi][1], ah[mi][2], ah[mi][3], bl0, bl1);    \
                    mma_bf16(acc[mi][ni][0], acc[mi][ni][1],                           \
                             acc[mi][ni][2], acc[mi][ni][3],                           \
                             al[mi][0], al[mi][1], al[mi][2], al[mi][3], bh0, bh1);    \
                }                                                                      \
            }                                                                          \
        }                                                                              \
    }

// ---------------------------------------------------------------------------
// Fused QKV projection (split-precision). Epilogue routes by bn:
// Q/K: fused RoPE + tf32-round (flash consumes tf32-exact fp32); V: round.
// ---------------------------------------------------------------------------
__global__ void __launch_bounds__(128, 2) qkv_gemm_kernel(
    float* __restrict__ Qd, float* __restrict__ Kd, float* __restrict__ Vd,
    const float* __restrict__ cosb, const float* __restrict__ sinb)
{
    extern __shared__ uint32_t smw[];
    const int tid  = threadIdx.x;
    const int lane = tid & 31, warp = tid >> 5;
    const int wm = warp & 1, wn = warp >> 1;
    const int bm = blockIdx.y * GBM, bn = blockIdx.x * GBN;

    BF16_GEMM_MAINLOOP(g_Xhi, g_Xlo, g_Whi, g_Wlo)

    float* C; int N2, colbase; bool rope;
    if (bn < 4096)      { C = Qd; N2 = DIMM; colbase = bn;        rope = true;  }
    else if (bn < 5120) { C = Kd; N2 = KVD;  colbase = bn - 4096; rope = true;  }
    else                { C = Vd; N2 = KVD;  colbase = bn - 5120; rope = false; }

    #pragma unroll
    for (int mi = 0; mi < 4; ++mi) {
        int row = bm + wm * 64 + mi * 16 + (lane >> 2);
        #pragma unroll
        for (int ni = 0; ni < 8; ++ni) {
            int col = colbase + wn * 64 + ni * 8 + ((lane & 3) << 1);
            float v0 = acc[mi][ni][0], v1 = acc[mi][ni][1];
            float v2 = acc[mi][ni][2], v3 = acc[mi][ni][3];
            if (rope) {
                int i  = (col & 127) >> 1;
                int n0 = row & (SEQ - 1);
                int n1 = (row + 8) & (SEQ - 1);
                float c0r = cosb[n0 * 64 + i], s0r = sinb[n0 * 64 + i];
                float c1r = cosb[n1 * 64 + i], s1r = sinb[n1 * 64 + i];
                float o0 = v0 * c0r - v1 * s0r, o1 = v0 * s0r + v1 * c0r;
                float o2 = v2 * c1r - v3 * s1r, o3 = v2 * s1r + v3 * c1r;
                v0 = rtf(o0); v1 = rtf(o1); v2 = rtf(o2); v3 = rtf(o3);
            } else {
                v0 = rtf(v0); v1 = rtf(v1); v2 = rtf(v2); v3 = rtf(v3);
            }
            *reinterpret_cast<float2*>(C + (size_t)row * N2 + col)       = make_float2(v0, v1);
            *reinterpret_cast<float2*>(C + (size_t)(row + 8) * N2 + col) = make_float2(v2, v3);
        }
    }
}

// ---------------------------------------------------------------------------
// O projection (split-precision): out = O @ wo^T, plain fp32 store.
// ---------------------------------------------------------------------------
__global__ void __launch_bounds__(128, 2) oproj_gemm_kernel(float* __restrict__ C)
{
    extern __shared__ uint32_t smw[];
    const int tid  = threadIdx.x;
    const int lane = tid & 31, warp = tid >> 5;
    const int wm = warp & 1, wn = warp >> 1;
    const int bm = blockIdx.y * GBM, bn = blockIdx.x * GBN;

    BF16_GEMM_MAINLOOP(g_Ohi, g_Olo, g_WOhi, g_WOlo)

    #pragma unroll
    for (int mi = 0; mi < 4; ++mi) {
        int row = bm + wm * 64 + mi * 16 + (lane >> 2);
        #pragma unroll
        for (int ni = 0; ni < 8; ++ni) {
            int col = bn + wn * 64 + ni * 8 + ((lane & 3) << 1);
            *reinterpret_cast<float2*>(C + (size_t)row * DIMM + col) =
                make_float2(acc[mi][ni][0], acc[mi][ni][1]);
            *reinterpret_cast<float2*>(C + (size_t)(row + 8) * DIMM + col) =
                make_float2(acc[mi][ni][2], acc[mi][ni][3]);
        }
    }
}

// ---------------------------------------------------------------------------
// Flash attention (causal, GQA 4:1), head_dim=128 — tf32 path, unchanged
// except the O store now emits split-packed bf16 hi/lo pairs.
// ---------------------------------------------------------------------------
#define KS_ST 132
#define VS_ST 136
#define PS_ST 68
#define KBUF (64 * KS_ST)
#define VBUF (64 * VS_ST)
#define FLASH_SMEM ((2 * KBUF + 2 * VBUF + 128 * PS_ST) * 4)

__global__ void __launch_bounds__(256, 1) flash_kernel(
    const float* __restrict__ Q, const float* __restrict__ Kg,
    const float* __restrict__ Vg,
    uint32_t* __restrict__ Ohi, uint32_t* __restrict__ Olo)
{
    extern __shared__ float sm[];
    float* Ks = sm;                        // 2 x [64][132]
    float* Vs = Ks + 2 * KBUF;             // 2 x [64][136]
    float* Ps = Vs + 2 * VBUF;             // [128][68]

    const int tid = threadIdx.x, lane = tid & 31, warp = tid >> 5;
    const int qt = 15 - blockIdx.x;        // heavy (diagonal) tiles first
    const int bh = blockIdx.y;             // 0..63
    const int b = bh >> 5, h = bh & 31, kvh = h >> 2;
    const int q0 = qt * 128;
    const size_t tokbase = (size_t)b * SEQ;

    const float* Qb = Q  + tokbase * DIMM + (size_t)h   * 128;
    const float* Kb = Kg + tokbase * KVD  + (size_t)kvh * 128;
    const float* Vb = Vg + tokbase * KVD  + (size_t)kvh * 128;

    const int r0loc = warp * 16 + (lane >> 2);
    const int qrow0 = q0 + r0loc;
    const int qrow1 = qrow0 + 8;
    const float scale = 0.08838834764831845f;    // 1/sqrt(128)

    auto load_kv = [&](int t, int buf) {
        const float* Kp = Kb + (size_t)(t * 64) * KVD;
        const float* Vp = Vb + (size_t)(t * 64) * KVD;
        float* Kd = Ks + buf * KBUF;
        float* Vd = Vs + buf * VBUF;
        for (int e = tid; e < 2048; e += 256) {
            int r = e >> 5, c4 = (e & 31) << 2;
            cp_async16(Kd + r * KS_ST + c4, Kp + (size_t)r * KVD + c4);
            cp_async16(Vd + r * VS_ST + c4, Vp + (size_t)r * KVD + c4);
        }
        cp_async_commit();
    };

    load_kv(0, 0);

    // Q fragments -> registers (once per block)
    uint32_t qf[16][4];
    {
        const float* q0p = Qb + (size_t)qrow0 * DIMM + (lane & 3);
        const float* q1p = q0p + 8 * DIMM;
        #pragma unroll
        for (int g = 0; g < 16; ++g) {
            qf[g][0] = __float_as_uint(__ldg(q0p + 8 * g));
            qf[g][1] = __float_as_uint(__ldg(q1p + 8 * g));
            qf[g][2] = __float_as_uint(__ldg(q0p + 8 * g + 4));
            qf[g][3] = __float_as_uint(__ldg(q1p + 8 * g + 4));
        }
    }

    float m0 = -1e30f, m1 = -1e30f, l0 = 0.f, l1 = 0.f;
    float oacc[16][4];
    #pragma unroll
    for (int i = 0; i < 16; ++i) { oacc[i][0] = 0.f; oacc[i][1] = 0.f; oacc[i][2] = 0.f; oacc[i][3] = 0.f; }

    const int ntiles = 2 * qt + 2;
    for (int t = 0; t < ntiles; ++t) {
        const int buf = t & 1;
        __syncthreads();
        if (t + 1 < ntiles) {
            load_kv(t + 1, (t + 1) & 1);
            cp_async_wait<1>();
        } else {
            cp_async_wait<0>();
        }
        __syncthreads();

        const float* Kbuf = Ks + buf * KBUF;
        const float* Vbuf = Vs + buf * VBUF;

        // ---- S = Q K^T ----
        float sacc[8][4];
        #pragma unroll
        for (int i = 0; i < 8; ++i) { sacc[i][0] = 0.f; sacc[i][1] = 0.f; sacc[i][2] = 0.f; sacc[i][3] = 0.f; }
        #pragma unroll
        for (int g = 0; g < 16; ++g) {
            #pragma unroll
            for (int ni = 0; ni < 8; ++ni) {
                const uint32_t* kp = (const uint32_t*)(Kbuf + (ni * 8 + (lane >> 2)) * KS_ST + 8 * g + (lane & 3));
                mma_tf32(sacc[ni][0], sacc[ni][1], sacc[ni][2], sacc[ni][3],
                         qf[g][0], qf[g][1], qf[g][2], qf[g][3], kp[0], kp[4]);
            }
        }

        // ---- online softmax ----
        float tm0 = -1e30f, tm1 = -1e30f;
        #pragma unroll
        for (int ni = 0; ni < 8; ++ni) {
            int kg = t * 64 + ni * 8 + ((lane & 3) << 1);
            float v0 = (kg     <= qrow0) ? sacc[ni][0] * scale : -1e30f;
            float v1 = (kg + 1 <= qrow0) ? sacc[ni][1] * scale : -1e30f;
            float v2 = (kg     <= qrow1) ? sacc[ni][2] * scale : -1e30f;
            float v3 = (kg + 1 <= qrow1) ? sacc[ni][3] * scale : -1e30f;
            sacc[ni][0] = v0; sacc[ni][1] = v1; sacc[ni][2] = v2; sacc[ni][3] = v3;
            tm0 = fmaxf(tm0, fmaxf(v0, v1));
            tm1 = fmaxf(tm1, fmaxf(v2, v3));
        }
        tm0 = fmaxf(tm0, __shfl_xor_sync(0xffffffffu, tm0, 1));
        tm0 = fmaxf(tm0, __shfl_xor_sync(0xffffffffu, tm0, 2));
        tm1 = fmaxf(tm1, __shfl_xor_sync(0xffffffffu, tm1, 1));
        tm1 = fmaxf(tm1, __shfl_xor_sync(0xffffffffu, tm1, 2));

        float mn0 = fmaxf(m0, tm0), mn1 = fmaxf(m1, tm1);
        float a0 = __expf(m0 - mn0), a1 = __expf(m1 - mn1);
        float s0 = 0.f, s1 = 0.f;
        #pragma unroll
        for (int ni = 0; ni < 8; ++ni) {
            float p0 = __expf(sacc[ni][0] - mn0);
            float p1 = __expf(sacc[ni][1] - mn0);
            float p2 = __expf(sacc[ni][2] - mn1);
            float p3 = __expf(sacc[ni][3] - mn1);
            s0 += p0 + p1; s1 += p2 + p3;
            int col = ni * 8 + ((lane & 3) << 1);
            *reinterpret_cast<float2*>(Ps + r0loc * PS_ST + col)       = make_float2(rtf(p0), rtf(p1));
            *reinterpret_cast<float2*>(Ps + (r0loc + 8) * PS_ST + col) = make_float2(rtf(p2), rtf(p3));
        }
        s0 += __shfl_xor_sync(0xffffffffu, s0, 1);
        s0 += __shfl_xor_sync(0xffffffffu, s0, 2);
        s1 += __shfl_xor_sync(0xffffffffu, s1, 1);
        s1 += __shfl_xor_sync(0xffffffffu, s1, 2);
        l0 = l0 * a0 + s0;
        l1 = l1 * a1 + s1;
        m0 = mn0; m1 = mn1;
        #pragma unroll
        for (int i = 0; i < 16; ++i) {
            oacc[i][0] *= a0; oacc[i][1] *= a0; oacc[i][2] *= a1; oacc[i][3] *= a1;
        }
        __syncwarp();   // warp-private P band read back cross-lane below

        // ---- O += P V ----
        #pragma unroll
        for (int k0 = 0; k0 < 64; k0 += 8) {
            const uint32_t* pp = (const uint32_t*)(Ps + r0loc * PS_ST + k0 + (lane & 3));
            uint32_t af0 = pp[0];
            uint32_t af1 = pp[8 * PS_ST];
            uint32_t af2 = pp[4];
            uint32_t af3 = pp[8 * PS_ST + 4];
            #pragma unroll
            for (int ni = 0; ni < 16; ++ni) {
                const uint32_t* vp = (const uint32_t*)(Vbuf + (k0 + (lane & 3)) * VS_ST + ni * 8 + (lane >> 2));
                mma_tf32(oacc[ni][0], oacc[ni][1], oacc[ni][2], oacc[ni][3],
                         af0, af1, af2, af3, vp[0], vp[4 * VS_ST]);
            }
        }
    }

    // ---- write O as split-packed bf16 hi/lo pairs (pair = col/2) ----
    float i0 = 1.f / l0, i1 = 1.f / l1;
    size_t pr0 = (tokbase + qrow0) * KP + (size_t)h * 64;
    size_t pr1 = (tokbase + qrow1) * KP + (size_t)h * 64;
    #pragma unroll
    for (int ni = 0; ni < 16; ++ni) {
        int pair = ni * 4 + (lane & 3);
        uint32_t h0, l0w, h1, l1w;
        split_pack(oacc[ni][0] * i0, oacc[ni][1] * i0, h0, l0w);
        split_pack(oacc[ni][2] * i1, oacc[ni][3] * i1, h1, l1w);
        Ohi[pr0 + pair] = h0; Olo[pr0 + pair] = l0w;
        Ohi[pr1 + pair] = h1; Olo[pr1 + pair] = l1w;
    }
}

// ---------------------------------------------------------------------------
// Launch
// ---------------------------------------------------------------------------
extern "C" void kernel_launch(void* const* d_in, const int* in_sizes, int n_in,
                              void* d_out, int out_size) {
    const float* x    = (const float*)d_in[0];
    const float* wq   = (const float*)d_in[1];
    const float* wk   = (const float*)d_in[2];
    const float* wv   = (const float*)d_in[3];
    const float* wo   = (const float*)d_in[4];
    const float* cosb = (const float*)d_in[5];
    const float* sinb = (const float*)d_in[6];
    float* out = (float*)d_out;

    float *Qb, *Kb, *Vb;
    uint32_t *Xhi, *Xlo, *Whi, *Wlo, *WOhi, *WOlo, *Ohi, *Olo;
    cudaGetSymbolAddress((void**)&Qb,   g_Q);
    cudaGetSymbolAddress((void**)&Kb,   g_K);
    cudaGetSymbolAddress((void**)&Vb,   g_V);
    cudaGetSymbolAddress((void**)&Xhi,  g_Xhi);
    cudaGetSymbolAddress((void**)&Xlo,  g_Xlo);
    cudaGetSymbolAddress((void**)&Whi,  g_Whi);
    cudaGetSymbolAddress((void**)&Wlo,  g_Wlo);
    cudaGetSymbolAddress((void**)&WOhi, g_WOhi);
    cudaGetSymbolAddress((void**)&WOlo, g_WOlo);
    cudaGetSymbolAddress((void**)&Ohi,  g_Ohi);
    cudaGetSymbolAddress((void**)&Olo,  g_Olo);

    cudaFuncSetAttribute(qkv_gemm_kernel,   cudaFuncAttributeMaxDynamicSharedMemorySize, GEMM_SMEM);
    cudaFuncSetAttribute(oproj_gemm_kernel, cudaFuncAttributeMaxDynamicSharedMemorySize, GEMM_SMEM);
    cudaFuncSetAttribute(flash_kernel,      cudaFuncAttributeMaxDynamicSharedMemorySize, FLASH_SMEM);

    // split-precision packing prepass (wq|wk|wv concatenated into g_Whi/lo)
    {
        int px = TOKS * KP;            // 8M pairs
        int pq = DIMM * KP;            // 8M
        int pk = KVD * KP;             // 2M
        pack_bf16_kernel<<<px / 1024, 256>>>((const float2*)x,  Xhi,  Xlo);
        pack_bf16_kernel<<<pq / 1024, 256>>>((const float2*)wq, Whi,  Wlo);
        pack_bf16_kernel<<<pk / 1024, 256>>>((const float2*)wk, Whi + (size_t)4096 * KP, Wlo + (size_t)4096 * KP);
        pack_bf16_kernel<<<pk / 1024, 256>>>((const float2*)wv, Whi + (size_t)5120 * KP, Wlo + (size_t)5120 * KP);
        pack_bf16_kernel<<<pq / 1024, 256>>>((const float2*)wo, WOhi, WOlo);
    }

    dim3 gblk(128);
    // Fused Q|K|V projection (split-precision bf16), rope fused in epilogue
    qkv_gemm_kernel<<<dim3(NQKV / GBN, TOKS / GBM), gblk, GEMM_SMEM>>>(
        Qb, Kb, Vb, cosb, sinb);
    // causal GQA flash attention (tf32 path; O emitted split-packed)
    flash_kernel<<<dim3(16, 64), dim3(256), FLASH_SMEM>>>(Qb, Kb, Vb, Ohi, Olo);
    // output projection (split-precision bf16)
    oproj_gemm_kernel<<<dim3(DIMM / GBN, TOKS / GBM), gblk, GEMM_SMEM>>>(out);
}

// round 15
// speedup vs baseline: 1.3324x; 1.3324x over previous
#include <cuda_runtime.h>
#include <cstdint>

// ---------------------------------------------------------------------------
// Problem constants
// ---------------------------------------------------------------------------
#define DIMM 4096        // model dim (= N_HEAD * HEAD_DIM)
#define KVD  1024        // kv proj dim (= N_KV_HEAD * HEAD_DIM)
#define SEQ  2048
#define TOKS 4096        // B * SEQ
#define NQKV 6144        // fused projection width: 4096 Q + 1024 K + 1024 V

// ---------------------------------------------------------------------------
// Scratch (no cudaMalloc allowed). All tf32-exact unless noted.
// ---------------------------------------------------------------------------
__device__ float g_Q[TOKS * DIMM];    // 64 MB  (tf32-exact, rope fused in proj)
__device__ float g_K[TOKS * KVD];     // 16 MB  (tf32-exact, rope fused in proj)
__device__ float g_V[TOKS * KVD];     // 16 MB  (tf32-exact: epilogue rounds)
__device__ float g_O[TOKS * DIMM];    // 64 MB  (tf32-exact: flash rounds at store)
__device__ float g_X[TOKS * DIMM];    // 64 MB  rounded copy of x
__device__ float g_WQKV[NQKV * DIMM]; // 96 MB  rounded wq|wk|wv rows concatenated
__device__ float g_WO[DIMM * DIMM];   // 64 MB  rounded wo

// ---------------------------------------------------------------------------
// Helpers
// ---------------------------------------------------------------------------
__device__ __forceinline__ uint32_t f2tf(float f) {
    uint32_t r;
    asm volatile("cvt.rna.tf32.f32 %0, %1;" : "=r"(r) : "f"(f));
    return r;
}
__device__ __forceinline__ float rtf(float f) { return __uint_as_float(f2tf(f)); }

__device__ __forceinline__ void cp_async16(void* smem, const void* gmem) {
    uint32_t s = (uint32_t)__cvta_generic_to_shared(smem);
    asm volatile("cp.async.cg.shared.global [%0], [%1], 16;\n" :: "r"(s), "l"(gmem) : "memory");
}
__device__ __forceinline__ void cp_async_commit() {
    asm volatile("cp.async.commit_group;\n" ::: "memory");
}
template<int N>
__device__ __forceinline__ void cp_async_wait() {
    asm volatile("cp.async.wait_group %0;\n" :: "n"(N) : "memory");
}

// D += A(16x8, row) * B(8x8, col)  tf32 raw-bit inputs, f32 accum
__device__ __forceinline__ void mma_tf32(float& c0, float& c1, float& c2, float& c3,
                                         uint32_t a0, uint32_t a1, uint32_t a2, uint32_t a3,
                                         uint32_t b0, uint32_t b1) {
    asm volatile(
        "mma.sync.aligned.m16n8k8.row.col.f32.tf32.tf32.f32 "
        "{%0,%1,%2,%3}, {%4,%5,%6,%7}, {%8,%9}, {%0,%1,%2,%3};\n"
        : "+f"(c0), "+f"(c1), "+f"(c2), "+f"(c3)
        : "r"(a0), "r"(a1), "r"(a2), "r"(a3), "r"(b0), "r"(b1));
}

// ---------------------------------------------------------------------------
// tf32 rounding prepass: 4 float4 per thread (MLP=4), coalesced.
// ---------------------------------------------------------------------------
__global__ void round_tf32_kernel(const float4* __restrict__ src, float4* __restrict__ dst) {
    int base = blockIdx.x * 1024 + threadIdx.x;
    float4 v[4];
    #pragma unroll
    for (int j = 0; j < 4; ++j) v[j] = src[base + j * 256];
    #pragma unroll
    for (int j = 0; j < 4; ++j) {
        v[j].x = rtf(v[j].x); v[j].y = rtf(v[j].y);
        v[j].z = rtf(v[j].z); v[j].w = rtf(v[j].w);
    }
    #pragma unroll
    for (int j = 0; j < 4; ++j) dst[base + j * 256] = v[j];
}

// ---------------------------------------------------------------------------
// GEMM core (per-tile mainloop). Block tile 128x128x32, 128 threads = 4 warps
// (2x2 grid of 64x64 warp tiles), 2 CTAs/SM, double-buffered smem.
// Persistent CTAs: each CTA grid-strides over output tiles (x fastest -> A
// rows shared by consecutive tiles for L2 reuse). Buffer reuse across tile
// transitions is ordered by the top-of-mainloop __syncthreads.
// ---------------------------------------------------------------------------
#define GBM 128
#define GBN 128
#define GBK 32
#define GST 36

#define GEMM_MAINLOOP(A_, W_, K_)                                                      \
    float acc[4][8][4];                                                                \
    _Pragma("unroll")                                                                  \
    for (int i = 0; i < 4; ++i)                                                        \
        _Pragma("unroll")                                                              \
        for (int j = 0; j < 8; ++j) {                                                  \
            acc[i][j][0] = 0.f; acc[i][j][1] = 0.f;                                    \
            acc[i][j][2] = 0.f; acc[i][j][3] = 0.f;                                    \
        }                                                                              \
    const int T = (K_) / GBK;                                                          \
    {                                                                                  \
        const float* Ag = (A_) + (size_t)bm * (K_);                                    \
        const float* Wg = (W_) + (size_t)bn * (K_);                                    \
        _Pragma("unroll")                                                              \
        for (int e = tid; e < 1024; e += 128) {                                        \
            int r = e >> 3, c4 = (e & 7) << 2;                                         \
            cp_async16(As + r * GST + c4, Ag + (size_t)r * (K_) + c4);                 \
            cp_async16(Bs + r * GST + c4, Wg + (size_t)r * (K_) + c4);                 \
        }                                                                              \
        cp_async_commit();                                                             \
    }                                                                                  \
    for (int t = 0; t < T; ++t) {                                                      \
        cp_async_wait<0>();                                                            \
        __syncthreads();                                                               \
        if (t + 1 < T) {                                                               \
            const int buf = (t + 1) & 1;                                               \
            const float* Ag = (A_) + (size_t)bm * (K_) + (size_t)(t + 1) * GBK;        \
            const float* Wg = (W_) + (size_t)bn * (K_) + (size_t)(t + 1) * GBK;        \
            float* Ab2 = As + buf * GBM * GST;                                         \
            float* Bb2 = Bs + buf * GBN * GST;                                         \
            _Pragma("unroll")                                                          \
            for (int e = tid; e < 1024; e += 128) {                                    \
                int r = e >> 3, c4 = (e & 7) << 2;                                     \
                cp_async16(Ab2 + r * GST + c4, Ag + (size_t)r * (K_) + c4);            \
                cp_async16(Bb2 + r * GST + c4, Wg + (size_t)r * (K_) + c4);            \
            }                                                                          \
            cp_async_commit();                                                         \
        }                                                                              \
        const uint32_t* Ab = (const uint32_t*)(As + (t & 1) * GBM * GST);              \
        const uint32_t* Bb = (const uint32_t*)(Bs + (t & 1) * GBN * GST);              \
        _Pragma("unroll")                                                              \
        for (int k0 = 0; k0 < GBK; k0 += 8) {                                          \
            uint32_t af[4][4], bf[8][2];                                               \
            _Pragma("unroll")                                                          \
            for (int mi = 0; mi < 4; ++mi) {                                           \
                const uint32_t* p = Ab + (wm * 64 + mi * 16 + (lane >> 2)) * GST       \
                                       + k0 + (lane & 3);                              \
                af[mi][0] = p[0];                                                      \
                af[mi][1] = p[8 * GST];                                                \
                af[mi][2] = p[4];                                                      \
                af[mi][3] = p[8 * GST + 4];                                            \
            }                                                                          \
            _Pragma("unroll")                                                          \
            for (int ni = 0; ni < 8; ++ni) {                                           \
                const uint32_t* p = Bb + (wn * 64 + ni * 8 + (lane >> 2)) * GST        \
                                       + k0 + (lane & 3);                              \
                bf[ni][0] = p[0];                                                      \
                bf[ni][1] = p[4];                                                      \
            }                                                                          \
            _Pragma("unroll")                                                          \
            for (int mi = 0; mi < 4; ++mi)                                             \
                _Pragma("unroll")                                                      \
                for (int ni = 0; ni < 8; ++ni)                                         \
                    mma_tf32(acc[mi][ni][0], acc[mi][ni][1],                           \
                             acc[mi][ni][2], acc[mi][ni][3],                           \
                             af[mi][0], af[mi][1], af[mi][2], af[mi][3],               \
                             bf[ni][0], bf[ni][1]);                                    \
        }                                                                              \
    }

// ---------------------------------------------------------------------------
// Persistent fused QKV projection: tiles over (TOKS/128) x (NQKV/128).
// Epilogue routes by bn: Q/K rope+round, V round.
// ---------------------------------------------------------------------------
__global__ void __launch_bounds__(128, 2) qkv_gemm_kernel(
    const float* __restrict__ A, const float* __restrict__ W,
    float* __restrict__ Qd, float* __restrict__ Kd, float* __restrict__ Vd,
    const float* __restrict__ cosb, const float* __restrict__ sinb)
{
    extern __shared__ float sm[];
    float* As = sm;                       // 2 x [128][36]
    float* Bs = sm + 2 * GBM * GST;       // 2 x [128][36]

    const int tid  = threadIdx.x;
    const int lane = tid & 31, warp = tid >> 5;
    const int wm = warp & 1, wn = warp >> 1;
    const int NBN = NQKV / GBN;                    // 48
    const int NT  = NBN * (TOKS / GBM);            // 1536

    for (int tile = blockIdx.x; tile < NT; tile += gridDim.x) {
        const int bm = (tile / NBN) * GBM;
        const int bn = (tile % NBN) * GBN;

        GEMM_MAINLOOP(A, W, DIMM)

        float* C; int N2, colbase; bool rope;
        if (bn < 4096)      { C = Qd; N2 = DIMM; colbase = bn;        rope = true;  }
        else if (bn < 5120) { C = Kd; N2 = KVD;  colbase = bn - 4096; rope = true;  }
        else                { C = Vd; N2 = KVD;  colbase = bn - 5120; rope = false; }

        #pragma unroll
        for (int mi = 0; mi < 4; ++mi) {
            int row = bm + wm * 64 + mi * 16 + (lane >> 2);
            #pragma unroll
            for (int ni = 0; ni < 8; ++ni) {
                int col = colbase + wn * 64 + ni * 8 + ((lane & 3) << 1);
                float v0 = acc[mi][ni][0], v1 = acc[mi][ni][1];
                float v2 = acc[mi][ni][2], v3 = acc[mi][ni][3];
                if (rope) {
                    int i  = (col & 127) >> 1;
                    int n0 = row & (SEQ - 1);
                    int n1 = (row + 8) & (SEQ - 1);
                    float c0r = cosb[n0 * 64 + i], s0r = sinb[n0 * 64 + i];
                    float c1r = cosb[n1 * 64 + i], s1r = sinb[n1 * 64 + i];
                    float o0 = v0 * c0r - v1 * s0r, o1 = v0 * s0r + v1 * c0r;
                    float o2 = v2 * c1r - v3 * s1r, o3 = v2 * s1r + v3 * c1r;
                    v0 = rtf(o0); v1 = rtf(o1); v2 = rtf(o2); v3 = rtf(o3);
                } else {
                    v0 = rtf(v0); v1 = rtf(v1); v2 = rtf(v2); v3 = rtf(v3);
                }
                *reinterpret_cast<float2*>(C + (size_t)row * N2 + col)       = make_float2(v0, v1);
                *reinterpret_cast<float2*>(C + (size_t)(row + 8) * N2 + col) = make_float2(v2, v3);
            }
        }
    }
}

// ---------------------------------------------------------------------------
// Persistent O-projection GEMM (plain fp32 store).
// ---------------------------------------------------------------------------
__global__ void __launch_bounds__(128, 2) oproj_gemm_kernel(
    const float* __restrict__ A, const float* __restrict__ W, float* __restrict__ C)
{
    extern __shared__ float sm[];
    float* As = sm;
    float* Bs = sm + 2 * GBM * GST;

    const int tid  = threadIdx.x;
    const int lane = tid & 31, warp = tid >> 5;
    const int wm = warp & 1, wn = warp >> 1;
    const int NBN = DIMM / GBN;                    // 32
    const int NT  = NBN * (TOKS / GBM);            // 1024

    for (int tile = blockIdx.x; tile < NT; tile += gridDim.x) {
        const int bm = (tile / NBN) * GBM;
        const int bn = (tile % NBN) * GBN;

        GEMM_MAINLOOP(A, W, DIMM)

        #pragma unroll
        for (int mi = 0; mi < 4; ++mi) {
            int row = bm + wm * 64 + mi * 16 + (lane >> 2);
            #pragma unroll
            for (int ni = 0; ni < 8; ++ni) {
                int col = bn + wn * 64 + ni * 8 + ((lane & 3) << 1);
                *reinterpret_cast<float2*>(C + (size_t)row * DIMM + col) =
                    make_float2(acc[mi][ni][0], acc[mi][ni][1]);
                *reinterpret_cast<float2*>(C + (size_t)(row + 8) * DIMM + col) =
                    make_float2(acc[mi][ni][2], acc[mi][ni][3]);
            }
        }
    }
}

// ---------------------------------------------------------------------------
// Flash attention (causal, GQA 4:1), head_dim=128.
// Q fragments in registers; K/V double-buffered with one-tile-ahead prefetch.
// Mask hoisting: tiles strictly below the diagonal (t < 2*qt) skip the
// causal selects (provably identical values).
// ---------------------------------------------------------------------------
#define KS_ST 132
#define VS_ST 136
#define PS_ST 68
#define KBUF (64 * KS_ST)
#define VBUF (64 * VS_ST)
#define FLASH_SMEM ((2 * KBUF + 2 * VBUF + 128 * PS_ST) * 4)

__global__ void __launch_bounds__(256, 1) flash_kernel(
    const float* __restrict__ Q, const float* __restrict__ Kg,
    const float* __restrict__ Vg, float* __restrict__ O)
{
    extern __shared__ float sm[];
    float* Ks = sm;                        // 2 x [64][132]
    float* Vs = Ks + 2 * KBUF;             // 2 x [64][136]
    float* Ps = Vs + 2 * VBUF;             // [128][68]

    const int tid = threadIdx.x, lane = tid & 31, warp = tid >> 5;
    const int qt = 15 - blockIdx.x;        // heavy (diagonal) tiles first
    const int bh = blockIdx.y;             // 0..63
    const int b = bh >> 5, h = bh & 31, kvh = h >> 2;
    const int q0 = qt * 128;
    const size_t tokbase = (size_t)b * SEQ;

    const float* Qb = Q  + tokbase * DIMM + (size_t)h   * 128;
    const float* Kb = Kg + tokbase * KVD  + (size_t)kvh * 128;
    const float* Vb = Vg + tokbase * KVD  + (size_t)kvh * 128;

    const int r0loc = warp * 16 + (lane >> 2);
    const int qrow0 = q0 + r0loc;
    const int qrow1 = qrow0 + 8;
    const float scale = 0.08838834764831845f;    // 1/sqrt(128)

    auto load_kv = [&](int t, int buf) {
        const float* Kp = Kb + (size_t)(t * 64) * KVD;
        const float* Vp = Vb + (size_t)(t * 64) * KVD;
        float* Kd = Ks + buf * KBUF;
        float* Vd = Vs + buf * VBUF;
        for (int e = tid; e < 2048; e += 256) {
            int r = e >> 5, c4 = (e & 31) << 2;
            cp_async16(Kd + r * KS_ST + c4, Kp + (size_t)r * KVD + c4);
            cp_async16(Vd + r * VS_ST + c4, Vp + (size_t)r * KVD + c4);
        }
        cp_async_commit();
    };

    load_kv(0, 0);

    // Q fragments -> registers (once per block)
    uint32_t qf[16][4];
    {
        const float* q0p = Qb + (size_t)qrow0 * DIMM + (lane & 3);
        const float* q1p = q0p + 8 * DIMM;
        #pragma unroll
        for (int g = 0; g < 16; ++g) {
            qf[g][0] = __float_as_uint(__ldg(q0p + 8 * g));
            qf[g][1] = __float_as_uint(__ldg(q1p + 8 * g));
            qf[g][2] = __float_as_uint(__ldg(q0p + 8 * g + 4));
            qf[g][3] = __float_as_uint(__ldg(q1p + 8 * g + 4));
        }
    }

    float m0 = -1e30f, m1 = -1e30f, l0 = 0.f, l1 = 0.f;
    float oacc[16][4];
    #pragma unroll
    for (int i = 0; i < 16; ++i) { oacc[i][0] = 0.f; oacc[i][1] = 0.f; oacc[i][2] = 0.f; oacc[i][3] = 0.f; }

    const int ntiles = 2 * qt + 2;
    for (int t = 0; t < ntiles; ++t) {
        const int buf = t & 1;
        __syncthreads();
        if (t + 1 < ntiles) {
            load_kv(t + 1, (t + 1) & 1);
            cp_async_wait<1>();
        } else {
            cp_async_wait<0>();
        }
        __syncthreads();

        const float* Kbuf = Ks + buf * KBUF;
        const float* Vbuf = Vs + buf * VBUF;

        // ---- S = Q K^T ----
        float sacc[8][4];
        #pragma unroll
        for (int i = 0; i < 8; ++i) { sacc[i][0] = 0.f; sacc[i][1] = 0.f; sacc[i][2] = 0.f; sacc[i][3] = 0.f; }
        #pragma unroll
        for (int g = 0; g < 16; ++g) {
            #pragma unroll
            for (int ni = 0; ni < 8; ++ni) {
                const uint32_t* kp = (const uint32_t*)(Kbuf + (ni * 8 + (lane >> 2)) * KS_ST + 8 * g + (lane & 3));
                mma_tf32(sacc[ni][0], sacc[ni][1], sacc[ni][2], sacc[ni][3],
                         qf[g][0], qf[g][1], qf[g][2], qf[g][3], kp[0], kp[4]);
            }
        }

        // ---- online softmax (mask only on the 2 diagonal tiles) ----
        float tm0 = -1e30f, tm1 = -1e30f;
        if (t < 2 * qt) {
            #pragma unroll
            for (int ni = 0; ni < 8; ++ni) {
                float v0 = sacc[ni][0] * scale;
                float v1 = sacc[ni][1] * scale;
                float v2 = sacc[ni][2] * scale;
                float v3 = sacc[ni][3] * scale;
                sacc[ni][0] = v0; sacc[ni][1] = v1; sacc[ni][2] = v2; sacc[ni][3] = v3;
                tm0 = fmaxf(tm0, fmaxf(v0, v1));
                tm1 = fmaxf(tm1, fmaxf(v2, v3));
            }
        } else {
            #pragma unroll
            for (int ni = 0; ni < 8; ++ni) {
                int kg = t * 64 + ni * 8 + ((lane & 3) << 1);
                float v0 = (kg     <= qrow0) ? sacc[ni][0] * scale : -1e30f;
                float v1 = (kg + 1 <= qrow0) ? sacc[ni][1] * scale : -1e30f;
                float v2 = (kg     <= qrow1) ? sacc[ni][2] * scale : -1e30f;
                float v3 = (kg + 1 <= qrow1) ? sacc[ni][3] * scale : -1e30f;
                sacc[ni][0] = v0; sacc[ni][1] = v1; sacc[ni][2] = v2; sacc[ni][3] = v3;
                tm0 = fmaxf(tm0, fmaxf(v0, v1));
                tm1 = fmaxf(tm1, fmaxf(v2, v3));
            }
        }
        tm0 = fmaxf(tm0, __shfl_xor_sync(0xffffffffu, tm0, 1));
        tm0 = fmaxf(tm0, __shfl_xor_sync(0xffffffffu, tm0, 2));
        tm1 = fmaxf(tm1, __shfl_xor_sync(0xffffffffu, tm1, 1));
        tm1 = fmaxf(tm1, __shfl_xor_sync(0xffffffffu, tm1, 2));

        float mn0 = fmaxf(m0, tm0), mn1 = fmaxf(m1, tm1);
        float a0 = __expf(m0 - mn0), a1 = __expf(m1 - mn1);
        float s0 = 0.f, s1 = 0.f;
        #pragma unroll
        for (int ni = 0; ni < 8; ++ni) {
            float p0 = __expf(sacc[ni][0] - mn0);
            float p1 = __expf(sacc[ni][1] - mn0);
            float p2 = __expf(sacc[ni][2] - mn1);
            float p3 = __expf(sacc[ni][3] - mn1);
            s0 += p0 + p1; s1 += p2 + p3;
            int col = ni * 8 + ((lane & 3) << 1);
            *reinterpret_cast<float2*>(Ps + r0loc * PS_ST + col)       = make_float2(rtf(p0), rtf(p1));
            *reinterpret_cast<float2*>(Ps + (r0loc + 8) * PS_ST + col) = make_float2(rtf(p2), rtf(p3));
        }
        s0 += __shfl_xor_sync(0xffffffffu, s0, 1);
        s0 += __shfl_xor_sync(0xffffffffu, s0, 2);
        s1 += __shfl_xor_sync(0xffffffffu, s1, 1);
        s1 += __shfl_xor_sync(0xffffffffu, s1, 2);
        l0 = l0 * a0 + s0;
        l1 = l1 * a1 + s1;
        m0 = mn0; m1 = mn1;
        #pragma unroll
        for (int i = 0; i < 16; ++i) {
            oacc[i][0] *= a0; oacc[i][1] *= a0; oacc[i][2] *= a1; oacc[i][3] *= a1;
        }
        __syncwarp();   // warp-private P band read back cross-lane below

        // ---- O += P V ----
        #pragma unroll
        for (int k0 = 0; k0 < 64; k0 += 8) {
            const uint32_t* pp = (const uint32_t*)(Ps + r0loc * PS_ST + k0 + (lane & 3));
            uint32_t af0 = pp[0];
            uint32_t af1 = pp[8 * PS_ST];
            uint32_t af2 = pp[4];
            uint32_t af3 = pp[8 * PS_ST + 4];
            #pragma unroll
            for (int ni = 0; ni < 16; ++ni) {
                const uint32_t* vp = (const uint32_t*)(Vbuf + (k0 + (lane & 3)) * VS_ST + ni * 8 + (lane >> 2));
                mma_tf32(oacc[ni][0], oacc[ni][1], oacc[ni][2], oacc[ni][3],
                         af0, af1, af2, af3, vp[0], vp[4 * VS_ST]);
            }
        }
    }

    // ---- write O (token-major), rounded so the final GEMM needs no cvt ----
    float i0 = 1.f / l0, i1 = 1.f / l1;
    size_t gr0 = (tokbase + qrow0) * DIMM + (size_t)h * 128;
    size_t gr1 = (tokbase + qrow1) * DIMM + (size_t)h * 128;
    #pragma unroll
    for (int ni = 0; ni < 16; ++ni) {
        int col = ni * 8 + ((lane & 3) << 1);
        *reinterpret_cast<float2*>(O + gr0 + col) = make_float2(rtf(oacc[ni][0] * i0), rtf(oacc[ni][1] * i0));
        *reinterpret_cast<float2*>(O + gr1 + col) = make_float2(rtf(oacc[ni][2] * i1), rtf(oacc[ni][3] * i1));
    }
}

// ---------------------------------------------------------------------------
// Launch
// ---------------------------------------------------------------------------
extern "C" void kernel_launch(void* const* d_in, const int* in_sizes, int n_in,
                              void* d_out, int out_size) {
    const float* x    = (const float*)d_in[0];
    const float* wq   = (const float*)d_in[1];
    const float* wk   = (const float*)d_in[2];
    const float* wv   = (const float*)d_in[3];
    const float* wo   = (const float*)d_in[4];
    const float* cosb = (const float*)d_in[5];
    const float* sinb = (const float*)d_in[6];
    float* out = (float*)d_out;

    float *Qb, *Kb, *Vb, *Ob, *Xr, *Wqkv, *WOr;
    cudaGetSymbolAddress((void**)&Qb,   g_Q);
    cudaGetSymbolAddress((void**)&Kb,   g_K);
    cudaGetSymbolAddress((void**)&Vb,   g_V);
    cudaGetSymbolAddress((void**)&Ob,   g_O);
    cudaGetSymbolAddress((void**)&Xr,   g_X);
    cudaGetSymbolAddress((void**)&Wqkv, g_WQKV);
    cudaGetSymbolAddress((void**)&WOr,  g_WO);

    int nsm = 148;
    cudaDeviceGetAttribute(&nsm, cudaDevAttrMultiProcessorCount, 0);
    const int PGRID = 2 * nsm;   // persistent grid: exactly one wave at 2 CTAs/SM

    const int GEMM_SMEM = 2 * (GBM * GST + GBN * GST) * 4;                  // 73728
    cudaFuncSetAttribute(qkv_gemm_kernel,   cudaFuncAttributeMaxDynamicSharedMemorySize, GEMM_SMEM);
    cudaFuncSetAttribute(oproj_gemm_kernel, cudaFuncAttributeMaxDynamicSharedMemorySize, GEMM_SMEM);
    cudaFuncSetAttribute(flash_kernel,      cudaFuncAttributeMaxDynamicSharedMemorySize, FLASH_SMEM);

    // tf32 rounding prepass (4 float4/thread). wq|wk|wv concatenated in g_WQKV.
    {
        int n4x = TOKS * DIMM / 4;   // 4M
        int n4q = DIMM * DIMM / 4;   // 4M
        int n4k = KVD * DIMM / 4;    // 1M
        round_tf32_kernel<<<n4x / 1024, 256>>>((const float4*)x,  (float4*)Xr);
        round_tf32_kernel<<<n4q / 1024, 256>>>((const float4*)wq, (float4*)Wqkv);
        round_tf32_kernel<<<n4k / 1024, 256>>>((const float4*)wk, (float4*)(Wqkv + (size_t)4096 * DIMM));
        round_tf32_kernel<<<n4k / 1024, 256>>>((const float4*)wv, (float4*)(Wqkv + (size_t)5120 * DIMM));
        round_tf32_kernel<<<n4q / 1024, 256>>>((const float4*)wo, (float4*)WOr);
    }

    dim3 gblk(128);
    // Fused Q|K|V projection (persistent, rope fused in epilogue)
    qkv_gemm_kernel<<<PGRID, gblk, GEMM_SMEM>>>(Xr, Wqkv, Qb, Kb, Vb, cosb, sinb);
    // causal GQA flash attention (Q in registers, double-buffered K/V)
    flash_kernel<<<dim3(16, 64), dim3(256), FLASH_SMEM>>>(Qb, Kb, Vb, Ob);
    // output projection (persistent)
    oproj_gemm_kernel<<<PGRID, gblk, GEMM_SMEM>>>(Ob, WOr, out);
}